// round 3
// baseline (speedup 1.0000x reference)
#include <cuda_runtime.h>
#include <cstddef>

// Fused HybridSamplerConv, round 2:
//  - all 31 network params in __constant__ memory (folded into FMA operands,
//    no per-thread param LDGs, much lower register pressure)
//  - 4 samples per thread: 6 front-batched 128-bit loads + 2 stores
//    (MLP_p1=6) to cover DRAM latency.

struct Params {
    float cw[4];
    float cb;
    float w1[12];   // [3,4] row-major
    float b1[4];
    float w2[8];    // [4,2] row-major
    float b2[2];
};

__constant__ Params cp;

__device__ __forceinline__ float tanh_fast(float x) {
    float y;
    asm("tanh.approx.f32 %0, %1;" : "=f"(y) : "f"(x));
    return y;
}

__device__ __forceinline__ float sigmoid_fast(float x) {
    return 1.0f / (1.0f + __expf(-x));
}

// Process one sample -> (o0, o1)
__device__ __forceinline__ float2 sample(float in0, float in1, float4 d) {
    float logit = fmaf(d.x, cp.cw[0], fmaf(d.y, cp.cw[1],
                  fmaf(d.z, cp.cw[2], fmaf(d.w, cp.cw[3], cp.cb))));
    float conv = sigmoid_fast(logit);

    float h[4];
#pragma unroll
    for (int j = 0; j < 4; ++j) {
        float a = fmaf(in0, cp.w1[0 * 4 + j],
                  fmaf(in1, cp.w1[1 * 4 + j],
                  fmaf(conv, cp.w1[2 * 4 + j], cp.b1[j])));
        h[j] = tanh_fast(a);
    }

    float z0 = cp.b2[0], z1 = cp.b2[1];
#pragma unroll
    for (int j = 0; j < 4; ++j) {
        z0 = fmaf(h[j], cp.w2[j * 2 + 0], z0);
        z1 = fmaf(h[j], cp.w2[j * 2 + 1], z1);
    }

    float e = __expf(z1 - z0);
    float r = 1.0f / (1.0f + e);
    return make_float2(r, e * r);
}

__global__ void __launch_bounds__(256)
hybrid_sampler_kernel(const float4* __restrict__ inp,   // [B/2]: 2 samples per float4
                      const float4* __restrict__ data,  // [B]:   1 sample per float4
                      float4*       __restrict__ out,   // [B/2]: 2 samples per float4
                      int nquads)                       // B/4
{
    int i = blockIdx.x * blockDim.x + threadIdx.x;
    if (i >= nquads) return;

    // Front-batched streaming loads: 6x 128-bit (MLP_p1 = 6)
    float4 inA = inp[2 * i + 0];   // samples 0,1 inputs
    float4 inB = inp[2 * i + 1];   // samples 2,3 inputs
    float4 d0  = data[4 * i + 0];
    float4 d1  = data[4 * i + 1];
    float4 d2  = data[4 * i + 2];
    float4 d3  = data[4 * i + 3];

    float2 o0 = sample(inA.x, inA.y, d0);
    float2 o1 = sample(inA.z, inA.w, d1);
    float2 o2 = sample(inB.x, inB.y, d2);
    float2 o3 = sample(inB.z, inB.w, d3);

    out[2 * i + 0] = make_float4(o0.x, o0.y, o1.x, o1.y);
    out[2 * i + 1] = make_float4(o2.x, o2.y, o3.x, o3.y);
}

extern "C" void kernel_launch(void* const* d_in, const int* in_sizes, int n_in,
                              void* d_out, int out_size)
{
    const float* inp    = (const float*)d_in[0]; // [B,2]
    const float* data   = (const float*)d_in[1]; // [B,2,2]
    const float* conv_w = (const float*)d_in[2]; // [2,2]
    const float* conv_b = (const float*)d_in[3]; // scalar
    const float* w1     = (const float*)d_in[4]; // [3,4]
    const float* b1     = (const float*)d_in[5]; // [4]
    const float* w2     = (const float*)d_in[6]; // [4,2]
    const float* b2     = (const float*)d_in[7]; // [2]
    float* out          = (float*)d_out;         // [B,2]

    // Stage all params into constant memory (D2D memcpy nodes; capture-legal).
    cudaMemcpyToSymbolAsync(cp, conv_w, 4 * sizeof(float),  offsetof(Params, cw), cudaMemcpyDeviceToDevice);
    cudaMemcpyToSymbolAsync(cp, conv_b, 1 * sizeof(float),  offsetof(Params, cb), cudaMemcpyDeviceToDevice);
    cudaMemcpyToSymbolAsync(cp, w1,     12 * sizeof(float), offsetof(Params, w1), cudaMemcpyDeviceToDevice);
    cudaMemcpyToSymbolAsync(cp, b1,     4 * sizeof(float),  offsetof(Params, b1), cudaMemcpyDeviceToDevice);
    cudaMemcpyToSymbolAsync(cp, w2,     8 * sizeof(float),  offsetof(Params, w2), cudaMemcpyDeviceToDevice);
    cudaMemcpyToSymbolAsync(cp, b2,     2 * sizeof(float),  offsetof(Params, b2), cudaMemcpyDeviceToDevice);

    int B = in_sizes[0] / 2;   // samples
    int nquads = B / 4;        // 4 samples per thread (B = 4M, divisible)

    int threads = 256;
    int blocks = (nquads + threads - 1) / threads;

    hybrid_sampler_kernel<<<blocks, threads>>>(
        (const float4*)inp, (const float4*)data, (float4*)out, nquads);
}

// round 4
// speedup vs baseline: 1.1308x; 1.1308x over previous
#include <cuda_runtime.h>
#include <cstddef>

// Fused HybridSamplerConv, round 3:
//  - main kernel unchanged from R2 (20.2us, DRAM 68%, near BW roofline)
//  - param staging collapsed from 6 memcpy graph nodes to 2 nodes:
//      pack_params kernel (gathers 31 floats -> packed device buffer)
//      + ONE cudaMemcpyToSymbolAsync into __constant__.

struct Params {
    float cw[4];
    float cb;
    float w1[12];   // [3,4] row-major
    float b1[4];
    float w2[8];    // [4,2] row-major
    float b2[2];
};
// 31 floats, no padding.

__constant__ Params cp;
__device__ float g_packed[32];

__global__ void pack_params(const float* __restrict__ cw,
                            const float* __restrict__ cb,
                            const float* __restrict__ w1,
                            const float* __restrict__ b1,
                            const float* __restrict__ w2,
                            const float* __restrict__ b2)
{
    int t = threadIdx.x;
    float v = 0.0f;
    if      (t < 4)  v = cw[t];
    else if (t == 4) v = cb[0];
    else if (t < 17) v = w1[t - 5];
    else if (t < 21) v = b1[t - 17];
    else if (t < 29) v = w2[t - 21];
    else if (t < 31) v = b2[t - 29];
    if (t < 31) g_packed[t] = v;
}

__device__ __forceinline__ float tanh_fast(float x) {
    float y;
    asm("tanh.approx.f32 %0, %1;" : "=f"(y) : "f"(x));
    return y;
}

__device__ __forceinline__ float sigmoid_fast(float x) {
    return 1.0f / (1.0f + __expf(-x));
}

// Process one sample -> (o0, o1)
__device__ __forceinline__ float2 sample(float in0, float in1, float4 d) {
    float logit = fmaf(d.x, cp.cw[0], fmaf(d.y, cp.cw[1],
                  fmaf(d.z, cp.cw[2], fmaf(d.w, cp.cw[3], cp.cb))));
    float conv = sigmoid_fast(logit);

    float h[4];
#pragma unroll
    for (int j = 0; j < 4; ++j) {
        float a = fmaf(in0, cp.w1[0 * 4 + j],
                  fmaf(in1, cp.w1[1 * 4 + j],
                  fmaf(conv, cp.w1[2 * 4 + j], cp.b1[j])));
        h[j] = tanh_fast(a);
    }

    float z0 = cp.b2[0], z1 = cp.b2[1];
#pragma unroll
    for (int j = 0; j < 4; ++j) {
        z0 = fmaf(h[j], cp.w2[j * 2 + 0], z0);
        z1 = fmaf(h[j], cp.w2[j * 2 + 1], z1);
    }

    float e = __expf(z1 - z0);
    float r = 1.0f / (1.0f + e);
    return make_float2(r, e * r);
}

__global__ void __launch_bounds__(256)
hybrid_sampler_kernel(const float4* __restrict__ inp,   // [B/2]: 2 samples per float4
                      const float4* __restrict__ data,  // [B]:   1 sample per float4
                      float4*       __restrict__ out,   // [B/2]: 2 samples per float4
                      int nquads)                       // B/4
{
    int i = blockIdx.x * blockDim.x + threadIdx.x;
    if (i >= nquads) return;

    // Front-batched streaming loads: 6x 128-bit (MLP_p1 = 6)
    float4 inA = inp[2 * i + 0];   // samples 0,1 inputs
    float4 inB = inp[2 * i + 1];   // samples 2,3 inputs
    float4 d0  = data[4 * i + 0];
    float4 d1  = data[4 * i + 1];
    float4 d2  = data[4 * i + 2];
    float4 d3  = data[4 * i + 3];

    float2 o0 = sample(inA.x, inA.y, d0);
    float2 o1 = sample(inA.z, inA.w, d1);
    float2 o2 = sample(inB.x, inB.y, d2);
    float2 o3 = sample(inB.z, inB.w, d3);

    out[2 * i + 0] = make_float4(o0.x, o0.y, o1.x, o1.y);
    out[2 * i + 1] = make_float4(o2.x, o2.y, o3.x, o3.y);
}

extern "C" void kernel_launch(void* const* d_in, const int* in_sizes, int n_in,
                              void* d_out, int out_size)
{
    const float* inp    = (const float*)d_in[0]; // [B,2]
    const float* data   = (const float*)d_in[1]; // [B,2,2]
    const float* conv_w = (const float*)d_in[2]; // [2,2]
    const float* conv_b = (const float*)d_in[3]; // scalar
    const float* w1     = (const float*)d_in[4]; // [3,4]
    const float* b1     = (const float*)d_in[5]; // [4]
    const float* w2     = (const float*)d_in[6]; // [4,2]
    const float* b2     = (const float*)d_in[7]; // [2]
    float* out          = (float*)d_out;         // [B,2]

    // Node 1: gather the 31 scattered params into one packed device buffer.
    pack_params<<<1, 32>>>(conv_w, conv_b, w1, b1, w2, b2);

    // Node 2: one D2D copy packed buffer -> __constant__ Params.
    void* packed_ptr = nullptr;
    cudaGetSymbolAddress(&packed_ptr, g_packed);
    cudaMemcpyToSymbolAsync(cp, packed_ptr, sizeof(Params), 0,
                            cudaMemcpyDeviceToDevice);

    int B = in_sizes[0] / 2;   // samples
    int nquads = B / 4;        // 4 samples per thread (B = 4M, divisible)

    int threads = 256;
    int blocks = (nquads + threads - 1) / threads;

    hybrid_sampler_kernel<<<blocks, threads>>>(
        (const float4*)inp, (const float4*)data, (float4*)out, nquads);
}

// round 5
// speedup vs baseline: 1.5019x; 1.3282x over previous
#include <cuda_runtime.h>

// Fused HybridSamplerConv, round 4: ONE graph node.
// Params loaded inside the main kernel as 8 uniform vector LDGs (L1-broadcast),
// eliminating both staging nodes (pack kernel + memcpy-to-constant) whose
// per-replay overhead dominated rounds 2-3.

__device__ __forceinline__ float tanh_fast(float x) {
    float y;
    asm("tanh.approx.f32 %0, %1;" : "=f"(y) : "f"(x));
    return y;
}

__global__ void __launch_bounds__(256)
hybrid_sampler_kernel(const float4* __restrict__ inp,    // [B/2]: 2 samples per float4
                      const float4* __restrict__ data,   // [B]:   1 sample per float4
                      const float4* __restrict__ conv_w, // 4 floats
                      const float*  __restrict__ conv_b, // 1 float
                      const float4* __restrict__ w1v,    // 12 floats = 3 x float4 (rows)
                      const float4* __restrict__ b1v,    // 4 floats
                      const float4* __restrict__ w2v,    // 8 floats = 2 x float4
                      const float2* __restrict__ b2v,    // 2 floats
                      float4*       __restrict__ out,    // [B/2]
                      int nquads)                        // B/4
{
    int i = blockIdx.x * blockDim.x + threadIdx.x;
    if (i >= nquads) return;

    // --- streaming loads first: 6x 128-bit, front-batched (MLP_p1 = 6) ---
    float4 inA = inp[2 * i + 0];
    float4 inB = inp[2 * i + 1];
    float4 d0  = data[4 * i + 0];
    float4 d1  = data[4 * i + 1];
    float4 d2  = data[4 * i + 2];
    float4 d3  = data[4 * i + 3];

    // --- uniform parameter loads: 8 vector LDGs, L1-broadcast ---
    float4 cw  = __ldg(conv_w);
    float  cb  = __ldg(conv_b);
    float4 w1r0 = __ldg(w1v + 0);   // w1[0][0..3] (in0 weights)
    float4 w1r1 = __ldg(w1v + 1);   // w1[1][0..3] (in1 weights)
    float4 w1r2 = __ldg(w1v + 2);   // w1[2][0..3] (conv weights)
    float4 b1   = __ldg(b1v);
    float4 w2a  = __ldg(w2v + 0);   // (w2[0][0], w2[0][1], w2[1][0], w2[1][1])
    float4 w2b  = __ldg(w2v + 1);   // (w2[2][0], w2[2][1], w2[3][0], w2[3][1])
    float2 b2   = __ldg(b2v);

    float4 resA, resB;

#pragma unroll
    for (int s = 0; s < 4; ++s) {
        float in0, in1;
        float4 d;
        if      (s == 0) { in0 = inA.x; in1 = inA.y; d = d0; }
        else if (s == 1) { in0 = inA.z; in1 = inA.w; d = d1; }
        else if (s == 2) { in0 = inB.x; in1 = inB.y; d = d2; }
        else             { in0 = inB.z; in1 = inB.w; d = d3; }

        // conv 2x2 -> sigmoid (THRESHOLD = 0)
        float logit = fmaf(d.x, cw.x, fmaf(d.y, cw.y,
                      fmaf(d.z, cw.z, fmaf(d.w, cw.w, cb))));
        float conv = 1.0f / (1.0f + __expf(-logit));

        // h = tanh([in0, in1, conv] @ w1 + b1)
        float h0 = tanh_fast(fmaf(in0, w1r0.x, fmaf(in1, w1r1.x, fmaf(conv, w1r2.x, b1.x))));
        float h1 = tanh_fast(fmaf(in0, w1r0.y, fmaf(in1, w1r1.y, fmaf(conv, w1r2.y, b1.y))));
        float h2 = tanh_fast(fmaf(in0, w1r0.z, fmaf(in1, w1r1.z, fmaf(conv, w1r2.z, b1.z))));
        float h3 = tanh_fast(fmaf(in0, w1r0.w, fmaf(in1, w1r1.w, fmaf(conv, w1r2.w, b1.w))));

        // z = h @ w2 + b2
        float z0 = fmaf(h0, w2a.x, fmaf(h1, w2a.z, fmaf(h2, w2b.x, fmaf(h3, w2b.z, b2.x))));
        float z1 = fmaf(h0, w2a.y, fmaf(h1, w2a.w, fmaf(h2, w2b.y, fmaf(h3, w2b.w, b2.y))));

        // softmax over 2 (exact, symmetric)
        float e = __expf(z1 - z0);
        float r = 1.0f / (1.0f + e);
        float o0 = r, o1 = e * r;

        if      (s == 0) { resA.x = o0; resA.y = o1; }
        else if (s == 1) { resA.z = o0; resA.w = o1; }
        else if (s == 2) { resB.x = o0; resB.y = o1; }
        else             { resB.z = o0; resB.w = o1; }
    }

    out[2 * i + 0] = resA;
    out[2 * i + 1] = resB;
}

extern "C" void kernel_launch(void* const* d_in, const int* in_sizes, int n_in,
                              void* d_out, int out_size)
{
    const float* inp    = (const float*)d_in[0]; // [B,2]
    const float* data   = (const float*)d_in[1]; // [B,2,2]
    const float* conv_w = (const float*)d_in[2]; // [2,2]
    const float* conv_b = (const float*)d_in[3]; // scalar
    const float* w1     = (const float*)d_in[4]; // [3,4]
    const float* b1     = (const float*)d_in[5]; // [4]
    const float* w2     = (const float*)d_in[6]; // [4,2]
    const float* b2     = (const float*)d_in[7]; // [2]
    float* out          = (float*)d_out;         // [B,2]

    int B = in_sizes[0] / 2;   // samples
    int nquads = B / 4;        // 4 samples per thread

    int threads = 256;
    int blocks = (nquads + threads - 1) / threads;

    hybrid_sampler_kernel<<<blocks, threads>>>(
        (const float4*)inp, (const float4*)data,
        (const float4*)conv_w, conv_b,
        (const float4*)w1, (const float4*)b1,
        (const float4*)w2, (const float2*)b2,
        (float4*)out, nquads);
}